// round 17
// baseline (speedup 1.0000x reference)
#include <cuda_runtime.h>
#include <cuda_fp16.h>
#include <cstdint>

// Problem shape (fixed by the dataset)
#define NB_ 8
#define T_  200
#define U_  50
#define J_  512
#define V_  500
#define NT_ (NB_*T_)   // 1600
#define NU_ (NB_*U_)   // 400
// rows of the big GEMM: NT_*U_ = 80000 = 625 * 128

// Scratch
__device__ float g_encP[NT_*J_];     // [1600][512] projected enc (+bias)
__device__ float g_decP[NU_*J_];     // [400][512]  projected dec (+bias)
// W_out pre-packed fp16, PAIRED fragment order:
//   [gpair(32)][ks(32)][lane(32)] uint4
//   pair p covers natoms {2p, 2p+1}; lane: g=lane>>2, t=lane&3
//   .x={W[16p+g][k+2t..]} .y={W[16p+g][k+2t+8..]}
//   .z={W[16p+8+g][k+2t..]} .w={W[16p+8+g][k+2t+8..]}   (k = ks*16)
__device__ __align__(16) uint4 g_Bh[32*32*32];       // 512 KB
// Activations tanh(encP+decP) pre-packed to fp16 A-fragment order:
//   [mtile(625)][matom(8)][ks(32)][lane(32)] uint4
__device__ __align__(16) uint4 g_Ah[625*8*32*32];    // 82 MB

__device__ __forceinline__ uint32_t smem_u32(const void* p) {
    uint32_t a;
    asm("{ .reg .u64 t; cvta.to.shared.u64 t, %1; cvt.u32.u64 %0, t; }"
        : "=r"(a) : "l"(p));
    return a;
}
__device__ __forceinline__ float atanh_(float x) {
    float y;
    asm("tanh.approx.f32 %0, %1;" : "=f"(y) : "f"(x));
    return y;
}
__device__ __forceinline__ uint32_t h2u(float lo, float hi) {
    __half2 h = __floats2half2_rn(lo, hi);
    return *(uint32_t*)&h;
}
// split a float pair into fp16 hi + fp16 residual lo (packed half2 words)
__device__ __forceinline__ void split2(float a, float b, uint32_t& hi, uint32_t& lo) {
    __half ha = __float2half_rn(a), hb = __float2half_rn(b);
    float ra = a - __half2float(ha), rb = b - __half2float(hb);
    __half2 h = __halves2half2(ha, hb);
    __half2 l = __floats2half2_rn(ra, rb);
    hi = *(uint32_t*)&h;
    lo = *(uint32_t*)&l;
}

#define HMMA16816(ac, a0,a1,a2,a3, b0,b1)                                      \
    asm volatile(                                                              \
        "mma.sync.aligned.m16n8k16.row.col.f32.f16.f16.f32 "                   \
        "{%0,%1,%2,%3}, {%4,%5,%6,%7}, {%8,%9}, {%0,%1,%2,%3};"                \
        : "+f"((ac)[0]), "+f"((ac)[1]), "+f"((ac)[2]), "+f"((ac)[3])           \
        : "r"(a0), "r"(a1), "r"(a2), "r"(a3), "r"(b0), "r"(b1))

// ---------------------------------------------------------------------------
// W_out -> paired fp16 fragment order
// ---------------------------------------------------------------------------
__global__ __launch_bounds__(256) void pack_w(const float* __restrict__ W)
{
    const int idx  = blockIdx.x * 256 + threadIdx.x;   // 32768 total
    const int lane = idx & 31;
    const int ks   = (idx >> 5) & 31;
    const int gp   = idx >> 10;                         // 0..31
    const int g = lane >> 2, t = lane & 3;
    const int v0 = gp * 16 + g;          // natom 2p
    const int v1 = v0 + 8;               // natom 2p+1
    const int k = ks * 16 + 2 * t;
    float a0=0.f,a1=0.f,a2=0.f,a3=0.f, b0=0.f,b1=0.f,b2=0.f,b3=0.f;
    if (v0 < V_) {
        const float* r = W + (size_t)v0 * J_;
        a0 = r[k]; a1 = r[k+1]; a2 = r[k+8]; a3 = r[k+9];
    }
    if (v1 < V_) {
        const float* r = W + (size_t)v1 * J_;
        b0 = r[k]; b1 = r[k+1]; b2 = r[k+8]; b3 = r[k+9];
    }
    uint4 o;
    o.x = h2u(a0, a1);
    o.y = h2u(a2, a3);
    o.z = h2u(b0, b1);
    o.w = h2u(b2, b3);
    g_Bh[idx] = o;
}

// ---------------------------------------------------------------------------
// Activation kernel: act = fp16(tanh(encP+decP)), fragment order.
// Coarse threads: one thread = one (mt, ma, ks, g) = 4 lanes = 64B out.
// Loads are LDG.128 (32B sectors, fully used); stores 4x contiguous STG.128.
// 1,280,000 threads = 5000 blocks x 256.
// ---------------------------------------------------------------------------
__global__ __launch_bounds__(256) void act_kernel()
{
    const int idx = blockIdx.x * 256 + threadIdx.x;    // 1,280,000
    const int g   = idx & 7;
    const int ks  = (idx >> 3) & 31;
    const int ma  = (idx >> 8) & 7;
    const int mt  = idx >> 11;                         // 0..624

    const int row0 = mt * 128 + ma * 16 + g;
    const int row1 = row0 + 8;
    const int nt0 = row0 / U_;
    const int u0  = row0 - nt0 * U_;
    const int nt1 = row1 / U_;
    const int u1  = row1 - nt1 * U_;
    const float* encR0 = g_encP + (size_t)nt0 * J_;
    const float* decR0 = g_decP + ((size_t)(nt0 / T_) * U_ + u0) * J_;
    const float* encR1 = g_encP + (size_t)nt1 * J_;
    const float* decR1 = g_decP + ((size_t)(nt1 / T_) * U_ + u1) * J_;

    const int k = ks * 16;
    float e0v[16], d0v[16], e1v[16], d1v[16];
#pragma unroll
    for (int q = 0; q < 4; q++) {
        *(float4*)&e0v[q*4] = *(const float4*)(encR0 + k + q*4);
        *(float4*)&d0v[q*4] = *(const float4*)(decR0 + k + q*4);
        *(float4*)&e1v[q*4] = *(const float4*)(encR1 + k + q*4);
        *(float4*)&d1v[q*4] = *(const float4*)(decR1 + k + q*4);
    }
    float a0[16], a1[16];
#pragma unroll
    for (int i = 0; i < 16; i++) {
        a0[i] = atanh_(e0v[i] + d0v[i]);
        a1[i] = atanh_(e1v[i] + d1v[i]);
    }
    // write 4 lanes (t = 0..3), contiguous 64B
    uint4* outp = g_Ah + ((size_t)(mt * 8 + ma) * 32 + ks) * 32 + g * 4;
#pragma unroll
    for (int t = 0; t < 4; t++) {
        uint4 o;
        o.x = h2u(a0[2*t],     a0[2*t + 1]);
        o.y = h2u(a1[2*t],     a1[2*t + 1]);
        o.z = h2u(a0[2*t + 8], a0[2*t + 9]);
        o.w = h2u(a1[2*t + 8], a1[2*t + 9]);
        outp[t] = o;
    }
}

// ---------------------------------------------------------------------------
// Projection GEMM via split-fp16 HMMA (hi+lo, drop lo*lo; err ~2^-21):
//   C[m][j] = sum_k A[m][k] W[j][k] + bias[j],  K = 512
// CTA tile 64 rows x 64 cols; grid (8 jtiles, 32 mtiles: 25 enc + 7 dec).
// ---------------------------------------------------------------------------
__global__ __launch_bounds__(256) void proj_hmma(
    const float* __restrict__ enc, const float* __restrict__ Wenc,
    const float* __restrict__ benc, float* __restrict__ encP,
    const float* __restrict__ dec, const float* __restrict__ Wdec,
    const float* __restrict__ bdec, float* __restrict__ decP)
{
    __shared__ __align__(16) uint32_t Ah_s[1024], Al_s[1024];   // 4KB each
    __shared__ __align__(16) uint32_t Bh_s[1024], Bl_s[1024];   // 4KB each

    const float *A, *W, *bias; float* C; int M, m0;
    if (blockIdx.y < 25) { A = enc; W = Wenc; bias = benc; C = encP; M = NT_; m0 = blockIdx.y * 64; }
    else                 { A = dec; W = Wdec; bias = bdec; C = decP; M = NU_; m0 = (blockIdx.y - 25) * 64; }

    const int tid  = threadIdx.x;
    const int wid  = tid >> 5;
    const int lane = tid & 31;
    const int j0   = blockIdx.x * 64;
    const int warpM = wid & 3;
    const int warpN = wid >> 2;

    const int sa_m = (tid >> 5) & 3;
    const int sa_t = tid & 3;
    const int sa_lane = tid & 31;
    const int rowA0 = m0 + sa_m * 16 + ((tid >> 2) & 7);
    const int rowA1 = rowA0 + 8;
    const int ts    = tid & 127;
    const int sb_na = ts >> 4;
    const int sb_ksl = (ts >> 3) & 1;
    const int sb_lq = ts & 7;
    const int jW = j0 + sb_na * 8 + sb_lq;

    float acc[4][4];
#pragma unroll
    for (int j = 0; j < 4; j++)
#pragma unroll
        for (int c = 0; c < 4; c++) acc[j][c] = 0.f;

#pragma unroll 1
    for (int kc = 0; kc < 16; kc++) {
        const int k0 = kc * 32;
        if (tid < 128) {
            const float* r0p = A + (size_t)rowA0 * 512;
            const float* r1p = A + (size_t)rowA1 * 512;
            const bool ok0 = rowA0 < M, ok1 = rowA1 < M;
#pragma unroll
            for (int ksl = 0; ksl < 2; ksl++) {
                const int kb = k0 + ksl * 16 + 2 * sa_t;
                float2 z = make_float2(0.f, 0.f);
                float2 x0a = ok0 ? *(const float2*)(r0p + kb)     : z;
                float2 x0b = ok0 ? *(const float2*)(r0p + kb + 8) : z;
                float2 x1a = ok1 ? *(const float2*)(r1p + kb)     : z;
                float2 x1b = ok1 ? *(const float2*)(r1p + kb + 8) : z;
                uint4 hi, lo;
                split2(x0a.x, x0a.y, hi.x, lo.x);
                split2(x1a.x, x1a.y, hi.y, lo.y);
                split2(x0b.x, x0b.y, hi.z, lo.z);
                split2(x1b.x, x1b.y, hi.w, lo.w);
                const int idx = ((sa_m * 2 + ksl) * 32 + sa_lane) * 4;
                *(uint4*)&Ah_s[idx] = hi;
                *(uint4*)&Al_s[idx] = lo;
            }
        } else {
            const float* wr = W + (size_t)jW * 512;
            const int kb = k0 + sb_ksl * 16;
            float wv[16];
            *(float4*)&wv[0]  = *(const float4*)(wr + kb);
            *(float4*)&wv[4]  = *(const float4*)(wr + kb + 4);
            *(float4*)&wv[8]  = *(const float4*)(wr + kb + 8);
            *(float4*)&wv[12] = *(const float4*)(wr + kb + 12);
#pragma unroll
            for (int t = 0; t < 4; t++) {
                const int l = sb_lq * 4 + t;
                uint32_t hx, lx, hy, ly;
                split2(wv[2*t],     wv[2*t + 1], hx, lx);
                split2(wv[2*t + 8], wv[2*t + 9], hy, ly);
                const int idx = ((sb_na * 2 + sb_ksl) * 32 + l) * 2;
                Bh_s[idx] = hx; Bh_s[idx + 1] = hy;
                Bl_s[idx] = lx; Bl_s[idx + 1] = ly;
            }
        }
        __syncthreads();

#pragma unroll
        for (int ksl = 0; ksl < 2; ksl++) {
            const int aidx = ((warpM * 2 + ksl) * 32 + lane) * 4;
            const uint4 ah = *(const uint4*)&Ah_s[aidx];
            const uint4 al = *(const uint4*)&Al_s[aidx];
#pragma unroll
            for (int j = 0; j < 4; j++) {
                const int bidx = (((warpN * 4 + j) * 2 + ksl) * 32 + lane) * 2;
                const uint2 bh = *(const uint2*)&Bh_s[bidx];
                const uint2 bl = *(const uint2*)&Bl_s[bidx];
                HMMA16816(acc[j], ah.x, ah.y, ah.z, ah.w, bh.x, bh.y);
                HMMA16816(acc[j], ah.x, ah.y, ah.z, ah.w, bl.x, bl.y);
                HMMA16816(acc[j], al.x, al.y, al.z, al.w, bh.x, bh.y);
            }
        }
        __syncthreads();
    }

    const int rsub = lane >> 2;
    const int cp   = (lane & 3) * 2;
#pragma unroll
    for (int j = 0; j < 4; j++) {
        const int col = j0 + (warpN * 4 + j) * 8 + cp;
        const float2 bb = *(const float2*)(bias + col);
        const int m0r = m0 + warpM * 16 + rsub;
        if (m0r < M) {
            float2 o; o.x = acc[j][0] + bb.x; o.y = acc[j][1] + bb.y;
            *(float2*)(C + (size_t)m0r * 512 + col) = o;
        }
        if (m0r + 8 < M) {
            float2 o; o.x = acc[j][2] + bb.x; o.y = acc[j][3] + bb.y;
            *(float2*)(C + (size_t)(m0r + 8) * 512 + col) = o;
        }
    }
}

// ---------------------------------------------------------------------------
// Main kernel: pure fp16 GEMM. 128x128 CTA tile, 256 threads (8 warps),
// warp tile 32x64, BK=32 (R14-proven residency). A fragments come DIRECTLY
// from gmem (g_Ah is fragment-ordered) via LDG.128 with distance-1 register
// prefetch — A never touches smem, killing the LDS->HMMA dependency chain.
// B only in smem: 3 stages x 8KB cp.async, paired LDS.128 reads.
// grid (4, 625), 2 CTAs/SM (regs capped at 128).
// ---------------------------------------------------------------------------
__global__ __launch_bounds__(256, 2) void joiner_hmma(
    const float* __restrict__ bout,   // [500]
    float* __restrict__ out)          // [80000][500]
{
    __shared__ __align__(16) uint32_t smemB[3 * 2048];   // 24 KB

    const int tid  = threadIdx.x;
    const int wid  = tid >> 5;
    const int lane = tid & 31;
    const int mt   = blockIdx.y;               // 0..624
    const long r0  = (long)mt * 128;
    const int vt   = blockIdx.x;               // 0..3
    const int v0   = vt * 128;
    const int warpM = wid & 3;    // 32-row group (2 matoms)
    const int warpN = wid >> 2;   // 64-col group (8 natoms = 4 pairs)

    const uint32_t smemBase = smem_u32(smemB);
    const char* ah_base = (const char*)g_Ah + (long)mt * (8 * 32 * 32 * 16);
    const char* bh_base = (const char*)g_Bh;

    // B copy: 512 x 16B slots per chunk, 2 per thread
    auto copyB = [&](int kc, int st) {
        const uint32_t sb = smemBase + (uint32_t)st * 8192u;
#pragma unroll
        for (int q = 0; q < 2; q++) {
            const int s = tid * 2 + q;                  // 0..511
            const int bp = s >> 6, bksl = (s >> 5) & 1, blane = s & 31;
            const long  gb = (long)(((vt * 8 + bp) * 32 + 2 * kc + bksl) * 32 + blane) * 16;
            const uint32_t ob = sb + (uint32_t)(((bp * 2 + bksl) * 32 + blane) * 16);
            asm volatile("cp.async.cg.shared.global [%0], [%1], 16;"
                         :: "r"(ob), "l"(bh_base + gb));
        }
        asm volatile("cp.async.commit_group;" ::: "memory");
    };
    // A fragment load: gmem -> regs (4 x LDG.128, fully coalesced per warp)
    auto loadA = [&](int kc, uint4 (*Ar)[2]) {
#pragma unroll
        for (int mi = 0; mi < 2; mi++)
#pragma unroll
            for (int ksl = 0; ksl < 2; ksl++) {
                const long ga = (long)(((warpM * 2 + mi) * 32 + 2 * kc + ksl) * 32
                                       + lane) * 16;
                Ar[mi][ksl] = *(const uint4*)(ah_base + ga);
            }
    };

    float acc[2][8][4];
#pragma unroll
    for (int i = 0; i < 2; i++)
#pragma unroll
        for (int j = 0; j < 8; j++)
#pragma unroll
            for (int c = 0; c < 4; c++) acc[i][j][c] = 0.f;

    uint4 Abuf[2][2][2];     // ping-pong A fragments [parity][mi][ksl]

    // prologue
    copyB(0, 0);
    copyB(1, 1);
    loadA(0, Abuf[0]);

#pragma unroll 2
    for (int kc = 0; kc < 16; kc++) {
        // prefetch next chunk's A into the other parity (LDG in flight ~1 chunk)
        if (kc < 15) loadA(kc + 1, Abuf[(kc + 1) & 1]);

        if (kc < 14)
            asm volatile("cp.async.wait_group 1;" ::: "memory");
        else
            asm volatile("cp.async.wait_group 0;" ::: "memory");
        __syncthreads();

        if (kc < 14) copyB(kc + 2, (kc + 2) % 3);

        const uint32_t* Bb = smemB + (kc % 3) * 2048;
        const uint4 (*Ac)[2] = Abuf[kc & 1];
#pragma unroll
        for (int ksl = 0; ksl < 2; ksl++) {
#pragma unroll
            for (int h = 0; h < 2; h++) {
                // two paired B fragments -> 4 natoms (local j = 4h..4h+3)
                const uint4 p0 = *(const uint4*)
                    (Bb + (((warpN * 4 + 2*h + 0) * 2 + ksl) * 32 + lane) * 4);
                const uint4 p1 = *(const uint4*)
                    (Bb + (((warpN * 4 + 2*h + 1) * 2 + ksl) * 32 + lane) * 4);
#pragma unroll
                for (int mi = 0; mi < 2; mi++) {
                    const uint4 a = Ac[mi][ksl];
                    HMMA16816(acc[mi][4*h + 0], a.x, a.y, a.z, a.w, p0.x, p0.y);
                    HMMA16816(acc[mi][4*h + 1], a.x, a.y, a.z, a.w, p0.z, p0.w);
                    HMMA16816(acc[mi][4*h + 2], a.x, a.y, a.z, a.w, p1.x, p1.y);
                    HMMA16816(acc[mi][4*h + 3], a.x, a.y, a.z, a.w, p1.z, p1.w);
                }
            }
        }
    }

    // epilogue: registers -> gmem, +bias, float2 stores
    const int cpair = (lane & 3) * 2;
    const int rsub  = lane >> 2;
#pragma unroll
    for (int j = 0; j < 8; j++) {
        const int col = v0 + warpN * 64 + j * 8 + cpair;
        if (col >= V_) continue;                  // V_ even: pair never straddles
        const float2 bb = *(const float2*)(bout + col);
#pragma unroll
        for (int mi = 0; mi < 2; mi++) {
            const long rr = r0 + warpM * 32 + mi * 16 + rsub;
            float2 o0, o1;
            o0.x = acc[mi][j][0] + bb.x;
            o0.y = acc[mi][j][1] + bb.y;
            o1.x = acc[mi][j][2] + bb.x;
            o1.y = acc[mi][j][3] + bb.y;
            *(float2*)(out + rr * (long)V_ + col)       = o0;
            *(float2*)(out + (rr + 8) * (long)V_ + col) = o1;
        }
    }
}

// ---------------------------------------------------------------------------
extern "C" void kernel_launch(void* const* d_in, const int* in_sizes, int n_in,
                              void* d_out, int out_size)
{
    (void)in_sizes; (void)n_in; (void)out_size;
    const float* encoder_out = (const float*)d_in[0];  // [8,200,512]
    const float* decoder_out = (const float*)d_in[1];  // [8,50,512]
    const float* W_enc       = (const float*)d_in[2];  // [512,512]
    const float* b_enc       = (const float*)d_in[3];  // [512]
    const float* W_dec       = (const float*)d_in[4];  // [512,512]
    const float* b_dec       = (const float*)d_in[5];  // [512]
    const float* W_out       = (const float*)d_in[6];  // [500,512]
    const float* b_out       = (const float*)d_in[7];  // [500]
    float* out = (float*)d_out;                        // [8,200,50,500]

    float* encP = nullptr;
    float* decP = nullptr;
    cudaGetSymbolAddress((void**)&encP, g_encP);
    cudaGetSymbolAddress((void**)&decP, g_decP);

    // pack W_out to paired fp16 fragment order
    pack_w<<<128, 256>>>(W_out);

    // projections via split-fp16 HMMA (enc: 25 mtiles, dec: 7 mtiles)
    {
        dim3 grid(8, 32);
        proj_hmma<<<grid, 256>>>(encoder_out, W_enc, b_enc, encP,
                                 decoder_out, W_dec, b_dec, decP);
    }
    // activations: tanh(encP+decP) -> fp16 fragment-packed gmem
    act_kernel<<<5000, 256>>>();

    // main pure fp16 GEMM (A direct from gmem, B 3-stage cp.async)
    {
        dim3 grid(4, 625);   // N-tiles x M-tiles
        joiner_hmma<<<grid, 256>>>(b_out, out);
    }
}